// round 1
// baseline (speedup 1.0000x reference)
#include <cuda_runtime.h>
#include <cuda_bf16.h>
#include <math.h>

#define N_NODES 100000
#define N_EDGES 1600000
#define IN_C 128
#define HID_C 128
#define OUT_C 64
#define SCAN_BLOCKS 256   // 256 blocks * 512 threads covers 131072 >= N_NODES

// ---------------- scratch (static device globals; no allocation) ----------------
__device__ int   g_deg[N_NODES];
__device__ float g_dinv[N_NODES];
__device__ int   g_rowptr[N_NODES + 1];
__device__ int   g_cursor[N_NODES];
__device__ int   g_col[N_EDGES];
__device__ float g_wgt[N_EDGES];
__device__ int   g_blocksums[SCAN_BLOCKS];
__device__ __align__(16) float g_h1[(size_t)N_NODES * HID_C];
__device__ __align__(16) float g_a1[(size_t)N_NODES * HID_C];
__device__ __align__(16) float g_h2[(size_t)N_NODES * OUT_C];

// ---------------- degree ----------------
__global__ void k_init_deg() {
    int i = blockIdx.x * 256 + threadIdx.x;
    if (i < N_NODES) g_deg[i] = 1;  // self-loop
}

__global__ void k_count(const int* __restrict__ dst) {
    int e = blockIdx.x * 256 + threadIdx.x;
    if (e < N_EDGES) atomicAdd(&g_deg[dst[e]], 1);
}

// ---------------- exclusive scan of (deg-1) -> rowptr, plus dinv ----------------
__global__ void k_scan_part() {
    __shared__ int wsum[16];
    int tid = threadIdx.x;
    int lane = tid & 31, wid = tid >> 5;
    int i = blockIdx.x * 512 + tid;
    int c = 0;
    if (i < N_NODES) {
        int d = g_deg[i];
        g_dinv[i] = rsqrtf((float)d);
        c = d - 1;  // in-edge count (self-loop handled separately)
    }
    int v = c;
    #pragma unroll
    for (int o = 1; o < 32; o <<= 1) {
        int t = __shfl_up_sync(0xffffffffu, v, o);
        if (lane >= o) v += t;
    }
    if (lane == 31) wsum[wid] = v;
    __syncthreads();
    if (wid == 0) {
        int s = (lane < 16) ? wsum[lane] : 0;
        #pragma unroll
        for (int o = 1; o < 16; o <<= 1) {
            int t = __shfl_up_sync(0xffffffffu, s, o);
            if (lane >= o) s += t;
        }
        if (lane < 16) wsum[lane] = s;
    }
    __syncthreads();
    int off = (wid > 0) ? wsum[wid - 1] : 0;
    if (i < N_NODES) g_rowptr[i] = off + v - c;
    if (tid == 511) g_blocksums[blockIdx.x] = wsum[15];
}

__global__ void k_scan_top() {   // 1 block, 256 threads
    __shared__ int wsum[8];
    int tid = threadIdx.x;
    int lane = tid & 31, wid = tid >> 5;
    int v0 = g_blocksums[tid];
    int v = v0;
    #pragma unroll
    for (int o = 1; o < 32; o <<= 1) {
        int t = __shfl_up_sync(0xffffffffu, v, o);
        if (lane >= o) v += t;
    }
    if (lane == 31) wsum[wid] = v;
    __syncthreads();
    if (wid == 0) {
        int s = (lane < 8) ? wsum[lane] : 0;
        #pragma unroll
        for (int o = 1; o < 8; o <<= 1) {
            int t = __shfl_up_sync(0xffffffffu, s, o);
            if (lane >= o) s += t;
        }
        if (lane < 8) wsum[lane] = s;
    }
    __syncthreads();
    int off = (wid > 0) ? wsum[wid - 1] : 0;
    g_blocksums[tid] = off + v - v0;   // exclusive
}

__global__ void k_scan_add() {
    int i = blockIdx.x * 256 + threadIdx.x;
    if (i < N_NODES) {
        int r = g_rowptr[i] + g_blocksums[i >> 9];
        g_rowptr[i] = r;
        g_cursor[i] = r;
    }
    if (i == N_NODES) g_rowptr[N_NODES] = N_EDGES;
}

// ---------------- CSR fill ----------------
__global__ void k_fill(const int* __restrict__ src, const int* __restrict__ dst) {
    int e = blockIdx.x * 256 + threadIdx.x;
    if (e < N_EDGES) {
        int s = src[e];
        int d = dst[e];
        int pos = atomicAdd(&g_cursor[d], 1);
        g_col[pos] = s;
        g_wgt[pos] = g_dinv[s];
    }
}

// ---------------- GEMM1: h1 = x @ W1  (M=100k, K=128, N=128) ----------------
__global__ __launch_bounds__(256) void k_gemm1(const float* __restrict__ x,
                                               const float* __restrict__ W) {
    __shared__ float Ws[32 * 128];  // 16KB
    __shared__ float Xs[64 * 32];   // 8KB
    int tid = threadIdx.x;
    int row0 = blockIdx.x * 64;
    int cg = tid & 31;   // col group (float4)
    int rg = tid >> 5;   // row group of 8

    float4 acc[8];
    #pragma unroll
    for (int r = 0; r < 8; r++) acc[r] = make_float4(0.f, 0.f, 0.f, 0.f);

    for (int kc = 0; kc < 4; kc++) {
        __syncthreads();
        #pragma unroll
        for (int t = 0; t < 4; t++) {
            int idx = tid + t * 256;  // 0..1023 float4s of the 32x128 chunk
            ((float4*)Ws)[idx] = ((const float4*)W)[kc * 1024 + idx];
        }
        #pragma unroll
        for (int t = 0; t < 2; t++) {
            int idx = tid + t * 256;  // 0..511 float4s of 64x32 tile
            int r = idx >> 3, c4 = idx & 7;
            int gr = row0 + r;
            float4 val = make_float4(0.f, 0.f, 0.f, 0.f);
            if (gr < N_NODES) val = ((const float4*)x)[gr * 32 + kc * 8 + c4];
            ((float4*)Xs)[idx] = val;
        }
        __syncthreads();
        #pragma unroll
        for (int k = 0; k < 32; k++) {
            float4 wv = *(const float4*)&Ws[k * 128 + cg * 4];
            #pragma unroll
            for (int r = 0; r < 8; r++) {
                float xv = Xs[(rg * 8 + r) * 32 + k];
                acc[r].x = fmaf(xv, wv.x, acc[r].x);
                acc[r].y = fmaf(xv, wv.y, acc[r].y);
                acc[r].z = fmaf(xv, wv.z, acc[r].z);
                acc[r].w = fmaf(xv, wv.w, acc[r].w);
            }
        }
    }
    #pragma unroll
    for (int r = 0; r < 8; r++) {
        int gr = row0 + rg * 8 + r;
        if (gr < N_NODES) ((float4*)g_h1)[gr * 32 + cg] = acc[r];
    }
}

// ---------------- aggregate layer 1 + bias + relu ----------------
__global__ __launch_bounds__(256) void k_agg1(const float* __restrict__ b1) {
    int node = blockIdx.x * 8 + (threadIdx.x >> 5);
    if (node >= N_NODES) return;
    int lane = threadIdx.x & 31;
    float di = g_dinv[node];
    const float4* h4 = (const float4*)g_h1;
    float4 self = h4[node * 32 + lane];
    float4 acc = make_float4(di * self.x, di * self.y, di * self.z, di * self.w);
    int beg = g_rowptr[node];
    int end = g_rowptr[node + 1];
    for (int e = beg; e < end; e++) {
        int s = g_col[e];
        float w = g_wgt[e];
        float4 hv = h4[s * 32 + lane];
        acc.x = fmaf(w, hv.x, acc.x);
        acc.y = fmaf(w, hv.y, acc.y);
        acc.z = fmaf(w, hv.z, acc.z);
        acc.w = fmaf(w, hv.w, acc.w);
    }
    float4 bv = ((const float4*)b1)[lane];
    float4 out;
    out.x = fmaxf(fmaf(acc.x, di, bv.x), 0.f);
    out.y = fmaxf(fmaf(acc.y, di, bv.y), 0.f);
    out.z = fmaxf(fmaf(acc.z, di, bv.z), 0.f);
    out.w = fmaxf(fmaf(acc.w, di, bv.w), 0.f);
    ((float4*)g_a1)[node * 32 + lane] = out;
}

// ---------------- GEMM2: h2 = a1 @ W2  (M=100k, K=128, N=64) ----------------
__global__ __launch_bounds__(256) void k_gemm2(const float* __restrict__ W2) {
    __shared__ float Ws[32 * 64];   // 8KB
    __shared__ float Xs[128 * 32];  // 16KB
    int tid = threadIdx.x;
    int row0 = blockIdx.x * 128;
    int cg = tid & 15;   // 16 float4 col groups
    int rg = tid >> 4;   // 16 row groups of 8

    float4 acc[8];
    #pragma unroll
    for (int r = 0; r < 8; r++) acc[r] = make_float4(0.f, 0.f, 0.f, 0.f);

    for (int kc = 0; kc < 4; kc++) {
        __syncthreads();
        #pragma unroll
        for (int t = 0; t < 2; t++) {
            int idx = tid + t * 256;  // 0..511 float4s of 32x64 chunk
            ((float4*)Ws)[idx] = ((const float4*)W2)[kc * 512 + idx];
        }
        #pragma unroll
        for (int t = 0; t < 4; t++) {
            int idx = tid + t * 256;  // 0..1023 float4s of 128x32 tile
            int r = idx >> 3, c4 = idx & 7;
            int gr = row0 + r;
            float4 val = make_float4(0.f, 0.f, 0.f, 0.f);
            if (gr < N_NODES) val = ((const float4*)g_a1)[gr * 32 + kc * 8 + c4];
            ((float4*)Xs)[idx] = val;
        }
        __syncthreads();
        #pragma unroll
        for (int k = 0; k < 32; k++) {
            float4 wv = *(const float4*)&Ws[k * 64 + cg * 4];
            #pragma unroll
            for (int r = 0; r < 8; r++) {
                float xv = Xs[(rg * 8 + r) * 32 + k];
                acc[r].x = fmaf(xv, wv.x, acc[r].x);
                acc[r].y = fmaf(xv, wv.y, acc[r].y);
                acc[r].z = fmaf(xv, wv.z, acc[r].z);
                acc[r].w = fmaf(xv, wv.w, acc[r].w);
            }
        }
    }
    #pragma unroll
    for (int r = 0; r < 8; r++) {
        int gr = row0 + rg * 8 + r;
        if (gr < N_NODES) ((float4*)g_h2)[gr * 16 + cg] = acc[r];
    }
}

// ---------------- aggregate layer 2 + bias + log_softmax ----------------
__global__ __launch_bounds__(256) void k_agg2(const float* __restrict__ b2,
                                              float* __restrict__ out) {
    int node = blockIdx.x * 8 + (threadIdx.x >> 5);
    if (node >= N_NODES) return;
    int lane = threadIdx.x & 31;
    float di = g_dinv[node];
    const float2* h2 = (const float2*)g_h2;
    float2 self = h2[node * 32 + lane];
    float2 acc = make_float2(di * self.x, di * self.y);
    int beg = g_rowptr[node];
    int end = g_rowptr[node + 1];
    for (int e = beg; e < end; e++) {
        int s = g_col[e];
        float w = g_wgt[e];
        float2 hv = h2[s * 32 + lane];
        acc.x = fmaf(w, hv.x, acc.x);
        acc.y = fmaf(w, hv.y, acc.y);
    }
    float2 bv = ((const float2*)b2)[lane];
    float vx = fmaf(acc.x, di, bv.x);
    float vy = fmaf(acc.y, di, bv.y);

    // log_softmax over 64 values held by the warp (2 per lane)
    float m = fmaxf(vx, vy);
    #pragma unroll
    for (int o = 16; o > 0; o >>= 1) m = fmaxf(m, __shfl_xor_sync(0xffffffffu, m, o));
    float s = expf(vx - m) + expf(vy - m);
    #pragma unroll
    for (int o = 16; o > 0; o >>= 1) s += __shfl_xor_sync(0xffffffffu, s, o);
    float lse = m + logf(s);
    float2 res = make_float2(vx - lse, vy - lse);
    ((float2*)out)[node * 32 + lane] = res;
}

// ---------------- launch ----------------
extern "C" void kernel_launch(void* const* d_in, const int* in_sizes, int n_in,
                              void* d_out, int out_size) {
    const float* x   = (const float*)d_in[0];
    const int*   ei  = (const int*)d_in[1];
    const float* W1  = (const float*)d_in[2];
    const float* b1  = (const float*)d_in[3];
    const float* W2  = (const float*)d_in[4];
    const float* b2  = (const float*)d_in[5];
    float* out = (float*)d_out;

    const int* src = ei;            // edge_index[0]
    const int* dst = ei + N_EDGES;  // edge_index[1]

    k_init_deg<<<(N_NODES + 255) / 256, 256>>>();
    k_count<<<(N_EDGES + 255) / 256, 256>>>(dst);
    k_scan_part<<<SCAN_BLOCKS, 512>>>();
    k_scan_top<<<1, 256>>>();
    k_scan_add<<<(N_NODES + 256) / 256, 256>>>();
    k_fill<<<(N_EDGES + 255) / 256, 256>>>(src, dst);

    k_gemm1<<<(N_NODES + 63) / 64, 256>>>(x, W1);
    k_agg1<<<(N_NODES + 7) / 8, 256>>>(b1);
    k_gemm2<<<(N_NODES + 127) / 128, 256>>>(W2);
    k_agg2<<<(N_NODES + 7) / 8, 256>>>(b2, out);
}

// round 3
// speedup vs baseline: 1.0131x; 1.0131x over previous
#include <cuda_runtime.h>
#include <cuda_bf16.h>
#include <cstdint>
#include <math.h>

#define N_NODES 100000
#define N_EDGES 1600000
#define IN_C 128
#define HID_C 128
#define OUT_C 64
#define SCAN_BLOCKS 256

// ---------------- scratch (static device globals; no allocation) ----------------
__device__ int   g_deg[N_NODES];
__device__ float g_dinv[N_NODES];
__device__ int   g_rowptr[N_NODES + 1];
__device__ int   g_cursor[N_NODES];
__device__ int   g_col[N_EDGES];
__device__ float g_wgt[N_EDGES];
__device__ int   g_blocksums[SCAN_BLOCKS];
__device__ __align__(16) float g_h1[(size_t)N_NODES * HID_C];
__device__ __align__(16) float g_a1[(size_t)N_NODES * HID_C];
__device__ __align__(16) float g_h2[(size_t)N_NODES * OUT_C];
// hi/lo bf16 weights in B-operand orientation: Bs[n][k] = W[k][n]
__device__ __align__(16) __nv_bfloat16 g_w1hi[128 * 128];
__device__ __align__(16) __nv_bfloat16 g_w1lo[128 * 128];
__device__ __align__(16) __nv_bfloat16 g_w2hi[64 * 128];
__device__ __align__(16) __nv_bfloat16 g_w2lo[64 * 128];

// ---------------- degree / scan / CSR ----------------
__global__ void k_init_deg() {
    int i = blockIdx.x * 256 + threadIdx.x;
    if (i < N_NODES) g_deg[i] = 1;
}
__global__ void k_count(const int* __restrict__ dst) {
    int e = blockIdx.x * 256 + threadIdx.x;
    if (e < N_EDGES) atomicAdd(&g_deg[dst[e]], 1);
}
__global__ void k_scan_part() {
    __shared__ int wsum[16];
    int tid = threadIdx.x;
    int lane = tid & 31, wid = tid >> 5;
    int i = blockIdx.x * 512 + tid;
    int c = 0;
    if (i < N_NODES) {
        int d = g_deg[i];
        g_dinv[i] = rsqrtf((float)d);
        c = d - 1;
    }
    int v = c;
    #pragma unroll
    for (int o = 1; o < 32; o <<= 1) {
        int t = __shfl_up_sync(0xffffffffu, v, o);
        if (lane >= o) v += t;
    }
    if (lane == 31) wsum[wid] = v;
    __syncthreads();
    if (wid == 0) {
        int s = (lane < 16) ? wsum[lane] : 0;
        #pragma unroll
        for (int o = 1; o < 16; o <<= 1) {
            int t = __shfl_up_sync(0xffffffffu, s, o);
            if (lane >= o) s += t;
        }
        if (lane < 16) wsum[lane] = s;
    }
    __syncthreads();
    int off = (wid > 0) ? wsum[wid - 1] : 0;
    if (i < N_NODES) g_rowptr[i] = off + v - c;
    if (tid == 511) g_blocksums[blockIdx.x] = wsum[15];
}
__global__ void k_scan_top() {
    __shared__ int wsum[8];
    int tid = threadIdx.x;
    int lane = tid & 31, wid = tid >> 5;
    int v0 = g_blocksums[tid];
    int v = v0;
    #pragma unroll
    for (int o = 1; o < 32; o <<= 1) {
        int t = __shfl_up_sync(0xffffffffu, v, o);
        if (lane >= o) v += t;
    }
    if (lane == 31) wsum[wid] = v;
    __syncthreads();
    if (wid == 0) {
        int s = (lane < 8) ? wsum[lane] : 0;
        #pragma unroll
        for (int o = 1; o < 8; o <<= 1) {
            int t = __shfl_up_sync(0xffffffffu, s, o);
            if (lane >= o) s += t;
        }
        if (lane < 8) wsum[lane] = s;
    }
    __syncthreads();
    int off = (wid > 0) ? wsum[wid - 1] : 0;
    g_blocksums[tid] = off + v - v0;
}
__global__ void k_scan_add() {
    int i = blockIdx.x * 256 + threadIdx.x;
    if (i < N_NODES) {
        int r = g_rowptr[i] + g_blocksums[i >> 9];
        g_rowptr[i] = r;
        g_cursor[i] = r;
    }
    if (i == N_NODES) g_rowptr[N_NODES] = N_EDGES;
}
__global__ void k_fill(const int* __restrict__ src, const int* __restrict__ dst) {
    int e = blockIdx.x * 256 + threadIdx.x;
    if (e < N_EDGES) {
        int s = src[e];
        int d = dst[e];
        int pos = atomicAdd(&g_cursor[d], 1);
        g_col[pos] = s;
        g_wgt[pos] = g_dinv[s];
    }
}

// ---------------- prep: split W into bf16 hi/lo, [n][k] orientation ----------------
__global__ void k_prep_w(const float* __restrict__ W1, const float* __restrict__ W2) {
    int i = blockIdx.x * 256 + threadIdx.x;
    if (i < 128 * 128) {
        int k = i >> 7, n = i & 127;
        float v = W1[i];
        __nv_bfloat16 h = __float2bfloat16(v);
        __nv_bfloat16 l = __float2bfloat16(v - __bfloat162float(h));
        g_w1hi[n * 128 + k] = h;
        g_w1lo[n * 128 + k] = l;
    } else if (i < 128 * 128 + 64 * 128) {
        int j = i - 128 * 128;
        int k = j >> 6, n = j & 63;
        float v = W2[j];
        __nv_bfloat16 h = __float2bfloat16(v);
        __nv_bfloat16 l = __float2bfloat16(v - __bfloat162float(h));
        g_w2hi[n * 128 + k] = h;
        g_w2lo[n * 128 + k] = l;
    }
}

// ---------------- bf16 mma.sync helper ----------------
__device__ __forceinline__ void mma_bf16(float& d0, float& d1, float& d2, float& d3,
                                         uint32_t a0, uint32_t a1, uint32_t a2, uint32_t a3,
                                         uint32_t b0, uint32_t b1) {
    asm volatile(
        "mma.sync.aligned.m16n8k16.row.col.f32.bf16.bf16.f32 "
        "{%0,%1,%2,%3}, {%4,%5,%6,%7}, {%8,%9}, {%0,%1,%2,%3};"
        : "+f"(d0), "+f"(d1), "+f"(d2), "+f"(d3)
        : "r"(a0), "r"(a1), "r"(a2), "r"(a3), "r"(b0), "r"(b1));
}

__device__ __forceinline__ uint32_t pack_hi2(float x, float y) {
    __nv_bfloat162 t = __halves2bfloat162(__float2bfloat16(x), __float2bfloat16(y));
    return *(uint32_t*)&t;
}
__device__ __forceinline__ uint32_t pack_lo2(float x, float y) {
    __nv_bfloat16 hx = __float2bfloat16(x), hy = __float2bfloat16(y);
    __nv_bfloat162 t = __halves2bfloat162(__float2bfloat16(x - __bfloat162float(hx)),
                                          __float2bfloat16(y - __bfloat162float(hy)));
    return *(uint32_t*)&t;
}

// ---------------- tensor-core GEMM via mma.sync: O = A @ W (M tile=128, K=128) ----------------
// smem rows padded to 136 bf16 (68 u32): stride 68 mod 32 == 4 -> conflict-free fragment LDS.
template<int NOUT>
__global__ __launch_bounds__(256) void k_mma_gemm(const float* __restrict__ Ain) {
    extern __shared__ uint32_t smu[];
    constexpr int STR = 68;                       // u32 per padded row
    constexpr int WMG = (NOUT == 128) ? 2 : 4;    // warp groups along M
    constexpr int TM  = 128 / WMG;                // warp tile M: 64 / 32
    constexpr int MT  = TM / 16;                  // 4 / 2
    constexpr int NT  = 4;                        // 4 * n8 = 32 cols per warp

    uint32_t* As_hi = smu;
    uint32_t* As_lo = As_hi + 128 * STR;
    uint32_t* Bs_hi = As_lo + 128 * STR;
    uint32_t* Bs_lo = Bs_hi + NOUT * STR;

    const int tid = threadIdx.x;
    const int wid = tid >> 5;
    const int lane = tid & 31;
    const int g = lane >> 2;
    const int tg = lane & 3;
    const int row0 = blockIdx.x * 128;

    const float* Asrc = (NOUT == 128) ? Ain : g_a1;
    const uint32_t* WhG = (NOUT == 128) ? (const uint32_t*)g_w1hi : (const uint32_t*)g_w2hi;
    const uint32_t* WlG = (NOUT == 128) ? (const uint32_t*)g_w1lo : (const uint32_t*)g_w2lo;

    // load + split A tile: 128 rows x 32 float4
    const float4* A4 = (const float4*)Asrc;
    #pragma unroll 4
    for (int t = 0; t < 16; t++) {
        int i = t * 256 + tid;
        int row = i >> 5, c4 = i & 31;
        int gr = row0 + row;
        float4 v = make_float4(0.f, 0.f, 0.f, 0.f);
        if (gr < N_NODES) v = A4[(size_t)gr * 32 + c4];
        uint32_t h01 = pack_hi2(v.x, v.y), h23 = pack_hi2(v.z, v.w);
        uint32_t l01 = pack_lo2(v.x, v.y), l23 = pack_lo2(v.z, v.w);
        *(uint2*)&As_hi[row * STR + c4 * 2] = make_uint2(h01, h23);
        *(uint2*)&As_lo[row * STR + c4 * 2] = make_uint2(l01, l23);
    }
    // copy weights (already hi/lo split, [n][k]) into padded smem
    for (int i = tid; i < NOUT * 64; i += 256) {
        int n = i >> 6, kp = i & 63;
        Bs_hi[n * STR + kp] = WhG[i];
        Bs_lo[n * STR + kp] = WlG[i];
    }
    __syncthreads();

    const int wm = (NOUT == 128) ? (wid & 1) : (wid & 3);
    const int wn = (NOUT == 128) ? (wid >> 1) : (wid >> 2);

    float d[MT][NT][4];
    #pragma unroll
    for (int mt = 0; mt < MT; mt++)
        #pragma unroll
        for (int nt = 0; nt < NT; nt++)
            #pragma unroll
            for (int j = 0; j < 4; j++) d[mt][nt][j] = 0.f;

    const uint32_t* Aterm[3] = {As_hi, As_hi, As_lo};
    const uint32_t* Bterm[3] = {Bs_hi, Bs_lo, Bs_hi};

    #pragma unroll
    for (int term = 0; term < 3; term++) {
        const uint32_t* Ab = Aterm[term] + (wm * TM + g) * STR;
        const uint32_t* Bb = Bterm[term] + (wn * 32 + g) * STR;
        #pragma unroll
        for (int ks = 0; ks < 8; ks++) {
            int ko = ks * 8 + tg;
            uint32_t a[MT][4], b[NT][2];
            #pragma unroll
            for (int mt = 0; mt < MT; mt++) {
                const uint32_t* Ar = Ab + mt * 16 * STR;
                a[mt][0] = Ar[ko];
                a[mt][1] = Ar[8 * STR + ko];
                a[mt][2] = Ar[ko + 4];
                a[mt][3] = Ar[8 * STR + ko + 4];
            }
            #pragma unroll
            for (int nt = 0; nt < NT; nt++) {
                const uint32_t* Br = Bb + nt * 8 * STR;
                b[nt][0] = Br[ko];
                b[nt][1] = Br[ko + 4];
            }
            #pragma unroll
            for (int mt = 0; mt < MT; mt++)
                #pragma unroll
                for (int nt = 0; nt < NT; nt++)
                    mma_bf16(d[mt][nt][0], d[mt][nt][1], d[mt][nt][2], d[mt][nt][3],
                             a[mt][0], a[mt][1], a[mt][2], a[mt][3],
                             b[nt][0], b[nt][1]);
        }
    }

    float* Odst = (NOUT == 128) ? g_h1 : g_h2;
    #pragma unroll
    for (int mt = 0; mt < MT; mt++) {
        int r0 = row0 + wm * TM + mt * 16 + g;
        #pragma unroll
        for (int nt = 0; nt < NT; nt++) {
            int c = wn * 32 + nt * 8 + tg * 2;
            if (r0 < N_NODES)
                *(float2*)&Odst[(size_t)r0 * NOUT + c] = make_float2(d[mt][nt][0], d[mt][nt][1]);
            if (r0 + 8 < N_NODES)
                *(float2*)&Odst[(size_t)(r0 + 8) * NOUT + c] = make_float2(d[mt][nt][2], d[mt][nt][3]);
        }
    }
}

// ---------------- aggregate layer 1 + bias + relu ----------------
__global__ __launch_bounds__(256) void k_agg1(const float* __restrict__ b1) {
    int node = blockIdx.x * 8 + (threadIdx.x >> 5);
    if (node >= N_NODES) return;
    int lane = threadIdx.x & 31;
    float di = g_dinv[node];
    const float4* h4 = (const float4*)g_h1;
    float4 self = h4[node * 32 + lane];
    float4 acc = make_float4(di * self.x, di * self.y, di * self.z, di * self.w);
    int beg = g_rowptr[node];
    int end = g_rowptr[node + 1];
    for (int e = beg; e < end; e++) {
        int s = g_col[e];
        float w = g_wgt[e];
        float4 hv = h4[s * 32 + lane];
        acc.x = fmaf(w, hv.x, acc.x);
        acc.y = fmaf(w, hv.y, acc.y);
        acc.z = fmaf(w, hv.z, acc.z);
        acc.w = fmaf(w, hv.w, acc.w);
    }
    float4 bv = ((const float4*)b1)[lane];
    float4 out;
    out.x = fmaxf(fmaf(acc.x, di, bv.x), 0.f);
    out.y = fmaxf(fmaf(acc.y, di, bv.y), 0.f);
    out.z = fmaxf(fmaf(acc.z, di, bv.z), 0.f);
    out.w = fmaxf(fmaf(acc.w, di, bv.w), 0.f);
    ((float4*)g_a1)[node * 32 + lane] = out;
}

// ---------------- aggregate layer 2 + bias + log_softmax ----------------
__global__ __launch_bounds__(256) void k_agg2(const float* __restrict__ b2,
                                              float* __restrict__ out) {
    int node = blockIdx.x * 8 + (threadIdx.x >> 5);
    if (node >= N_NODES) return;
    int lane = threadIdx.x & 31;
    float di = g_dinv[node];
    const float2* h2 = (const float2*)g_h2;
    float2 self = h2[node * 32 + lane];
    float2 acc = make_float2(di * self.x, di * self.y);
    int beg = g_rowptr[node];
    int end = g_rowptr[node + 1];
    for (int e = beg; e < end; e++) {
        int s = g_col[e];
        float w = g_wgt[e];
        float2 hv = h2[s * 32 + lane];
        acc.x = fmaf(w, hv.x, acc.x);
        acc.y = fmaf(w, hv.y, acc.y);
    }
    float2 bv = ((const float2*)b2)[lane];
    float vx = fmaf(acc.x, di, bv.x);
    float vy = fmaf(acc.y, di, bv.y);

    float m = fmaxf(vx, vy);
    #pragma unroll
    for (int o = 16; o > 0; o >>= 1) m = fmaxf(m, __shfl_xor_sync(0xffffffffu, m, o));
    float s = expf(vx - m) + expf(vy - m);
    #pragma unroll
    for (int o = 16; o > 0; o >>= 1) s += __shfl_xor_sync(0xffffffffu, s, o);
    float lse = m + logf(s);
    ((float2*)out)[node * 32 + lane] = make_float2(vx - lse, vy - lse);
}

// ---------------- launch ----------------
extern "C" void kernel_launch(void* const* d_in, const int* in_sizes, int n_in,
                              void* d_out, int out_size) {
    const float* x  = (const float*)d_in[0];
    const int*   ei = (const int*)d_in[1];
    const float* W1 = (const float*)d_in[2];
    const float* b1 = (const float*)d_in[3];
    const float* W2 = (const float*)d_in[4];
    const float* b2 = (const float*)d_in[5];
    float* out = (float*)d_out;

    const int* src = ei;
    const int* dst = ei + N_EDGES;

    const int SMEM1 = (2 * 128 * 68 + 2 * 128 * 68) * 4;  // 139264
    const int SMEM2 = (2 * 128 * 68 + 2 * 64 * 68) * 4;   // 104448
    cudaFuncSetAttribute(k_mma_gemm<128>, cudaFuncAttributeMaxDynamicSharedMemorySize, SMEM1);
    cudaFuncSetAttribute(k_mma_gemm<64>,  cudaFuncAttributeMaxDynamicSharedMemorySize, SMEM2);

    k_prep_w<<<(128 * 128 + 64 * 128 + 255) / 256, 256>>>(W1, W2);

    k_init_deg<<<(N_NODES + 255) / 256, 256>>>();
    k_count<<<(N_EDGES + 255) / 256, 256>>>(dst);
    k_scan_part<<<SCAN_BLOCKS, 512>>>();
    k_scan_top<<<1, 256>>>();
    k_scan_add<<<(N_NODES + 256) / 256, 256>>>();
    k_fill<<<(N_EDGES + 255) / 256, 256>>>(src, dst);

    const int NTILES = (N_NODES + 127) / 128;  // 782
    k_mma_gemm<128><<<NTILES, 256, SMEM1>>>(x);
    k_agg1<<<(N_NODES + 7) / 8, 256>>>(b1);
    k_mma_gemm<64><<<NTILES, 256, SMEM2>>>(nullptr);
    k_agg2<<<(N_NODES + 7) / 8, 256>>>(b2, out);
}